// round 2
// baseline (speedup 1.0000x reference)
#include <cuda_runtime.h>
#include <cstdint>

// ---- static problem config (matches reference) ----
#define BB     2
#define HH     16
#define LL     16384
#define DH     128
#define TPF    512
#define CAP    (LL + TPF)        // 16896
#define BSZ    128
#define NBUCK  32                // L / TPF / PD
#define ROWS   (2 * BB * HH)     // 64 (k/v component folded into row)
#define ROW_V4 (CAP * DH / 4)    // 540672 float4 per row
#define KVROW_V4 (TPF * DH / 4)  // 16384 float4 per row in kv
#define KVB    (CAP / BSZ)       // 132 kv blocks
#define QB     ((TPF + BSZ - 1) / BSZ)  // 4 q blocks

// 32-bit "truthy" test: works whether the bool array was materialized as
// int32 (0/1) or float32 (0.0/1.0) — both have all-zero bits iff false.
__device__ __forceinline__ bool truthy32(const unsigned int* p, int i) {
    return p[i] != 0u;
}

// Main copy: out[row, i] <- kv or kv_buf, float4-vectorized.
// pos (token slot) is warp-uniform because DH/4 = 32 float4 per token.
__global__ void __launch_bounds__(256)
kv_copy_kernel(const float4* __restrict__ kv,
               const float4* __restrict__ buf,
               const int*    __restrict__ t_pos,
               const int*    __restrict__ frozen_p,
               float4*       __restrict__ out)
{
    int i   = blockIdx.x * 256 + threadIdx.x;   // float4 idx within row
    int row = blockIdx.y;
    if (i >= ROW_V4) return;

    // PD = 1: bucket = frame_t, write_step always true.
    int frame_t   = __ldg(t_pos);
    int ring_base = (frame_t % NBUCK) * TPF;
    int frozen    = frozen_p ? __ldg(frozen_p) : 0;

    int pos = i >> 5;   // i / (DH/4)
    size_t oidx = (size_t)row * ROW_V4 + i;

    float4 val;
    if (pos >= LL) {
        // current-frame tail: always holds kv (index_copy before frozen check)
        val = kv[(size_t)row * KVROW_V4 + (i - LL * 32)];
    } else if (!frozen && pos >= ring_base && pos < ring_base + TPF) {
        // ring slot for this frame: written with kv when not frozen
        val = kv[(size_t)row * KVROW_V4 + (i - ring_base * 32)];
    } else {
        val = buf[oidx];
    }
    out[oidx] = val;
}

// Metadata: block mask + orderings + mask_written + written, ~35K floats.
__global__ void __launch_bounds__(256)
meta_kernel(const int*          __restrict__ t_pos,
            const unsigned int* __restrict__ written,   // 32-bit per element
            const int*          __restrict__ frozen_p,
            float*              __restrict__ out)
{
    __shared__ unsigned char s_any[KVB];
    __shared__ unsigned char s_all[KVB];
    int tid = threadIdx.x;

    int frame_t   = t_pos[0];
    int ring_base = (frame_t % NBUCK) * TPF;
    int frozen    = frozen_p ? frozen_p[0] : 0;
    // write_step == true (PD = 1)

    const size_t base = (size_t)2 * BB * HH * CAP * DH;  // 138412032
    const size_t off_kvnum  = base;
    const size_t off_kvidx  = base + QB;                     // +4
    const size_t off_fnum   = off_kvidx + (size_t)QB * KVB;  // +532
    const size_t off_fidx   = off_fnum + QB;                 // +536
    const size_t off_mask   = off_fidx + (size_t)QB * KVB;   // +1064
    const size_t off_wr     = off_mask + CAP;                // +17960

    // mask_written(p): ring range forced false (written & !write_step), else input
    // written_out(p): input | (!frozen && p in ring)   [dst = ring since write_step]
    for (int p = tid; p < CAP; p += 256) {
        bool w = truthy32(written, p);
        bool in_ring = (p >= ring_base) && (p < ring_base + TPF);
        bool mw = in_ring ? false : w;
        bool wr = w || (!frozen && in_ring);
        out[off_mask + p] = mw ? 1.0f : 0.0f;
        out[off_wr   + p] = wr ? 1.0f : 0.0f;
    }

    // per-128-token block any/all of mask_written
    for (int b = tid; b < KVB; b += 256) {
        unsigned char any_ = 0, all_ = 1;
        #pragma unroll 4
        for (int j = 0; j < BSZ; j++) {
            int p = b * BSZ + j;
            bool in_ring = (p >= ring_base) && (p < ring_base + TPF);
            unsigned char m = in_ring ? 0 : (truthy32(written, p) ? 1 : 0);
            any_ |= m;
            all_ &= m;
        }
        s_any[b] = any_;
        s_all[b] = all_;
    }
    __syncthreads();

    if (tid == 0) {
        int ord_p[KVB], ord_f[KVB];
        int np = 0, nf = 0;
        // stable: true-blocks first (original order), then false-blocks
        for (int b = 0; b < KVB; b++) {
            bool part = s_any[b] && !s_all[b];
            if (part) ord_p[np++] = b;
        }
        { int k = np;
          for (int b = 0; b < KVB; b++) {
              bool part = s_any[b] && !s_all[b];
              if (!part) ord_p[k++] = b;
          } }
        for (int b = 0; b < KVB; b++)
            if (s_all[b]) ord_f[nf++] = b;
        { int k = nf;
          for (int b = 0; b < KVB; b++)
              if (!s_all[b]) ord_f[k++] = b; }

        for (int q = 0; q < QB; q++) {
            out[off_kvnum + q] = (float)np;
            out[off_fnum  + q] = (float)nf;
            for (int b = 0; b < KVB; b++) {
                out[off_kvidx + (size_t)q * KVB + b] = (float)ord_p[b];
                out[off_fidx  + (size_t)q * KVB + b] = (float)ord_f[b];
            }
        }
    }
}

extern "C" void kernel_launch(void* const* d_in, const int* in_sizes, int n_in,
                              void* d_out, int out_size)
{
    const float4*       kv     = (const float4*)d_in[0];
    const float4*       buf    = (const float4*)d_in[1];
    const int*          t_pos  = (const int*)d_in[2];
    const unsigned int* wrt    = (const unsigned int*)d_in[3];
    const int*          frozen = (n_in > 4) ? (const int*)d_in[4] : nullptr;
    float* out = (float*)d_out;

    (void)in_sizes; (void)out_size;

    meta_kernel<<<1, 256>>>(t_pos, wrt, frozen, out);

    dim3 grid((ROW_V4 + 255) / 256, ROWS);   // (2112, 64)
    kv_copy_kernel<<<grid, 256>>>(kv, buf, t_pos, frozen, (float4*)out);
}

// round 3
// speedup vs baseline: 1.2397x; 1.2397x over previous
#include <cuda_runtime.h>
#include <cstdint>

// ---- static problem config (matches reference) ----
#define BB     2
#define HH     16
#define LL     16384
#define DH     128
#define TPF    512
#define CAP    (LL + TPF)        // 16896
#define BSZ    128
#define NBUCK  32                // L / TPF / PD
#define ROWS   (2 * BB * HH)     // 64 (k/v component folded into row)
#define ROW_V4 (CAP * DH / 4)    // 540672 float4 per row
#define KVROW_V4 (TPF * DH / 4)  // 16384 float4 per row in kv
#define KVB    (CAP / BSZ)       // 132 kv blocks
#define QB     ((TPF + BSZ - 1) / BSZ)  // 4 q blocks

#define CHUNK    1024                    // float4 per block (4 per thread)
#define NCHUNKS  (ROW_V4 / CHUNK)        // 528 exactly

__device__ __forceinline__ bool truthy32(const unsigned int* p, int i) {
    return p[i] != 0u;
}

// ---- metadata: block mask + orderings + mask_written + written ----
__device__ void do_meta(const int*          __restrict__ t_pos,
                        const unsigned int* __restrict__ written,
                        const int*          __restrict__ frozen_p,
                        float*              __restrict__ out)
{
    __shared__ unsigned char s_any[KVB];
    __shared__ unsigned char s_all[KVB];
    __shared__ short s_ordp[KVB];
    __shared__ short s_ordf[KVB];
    __shared__ int   s_np, s_nf;
    int tid = threadIdx.x;

    int frame_t   = t_pos[0];
    int ring_base = (frame_t % NBUCK) * TPF;
    int frozen    = frozen_p ? frozen_p[0] : 0;
    // write_step == true (PD = 1)

    const size_t base = (size_t)2 * BB * HH * CAP * DH;  // 138412032
    const size_t off_kvnum  = base;
    const size_t off_kvidx  = base + QB;
    const size_t off_fnum   = off_kvidx + (size_t)QB * KVB;
    const size_t off_fidx   = off_fnum + QB;
    const size_t off_mask   = off_fidx + (size_t)QB * KVB;
    const size_t off_wr     = off_mask + CAP;

    // mask_written / written_out, parallel + coalesced
    for (int p = tid; p < CAP; p += 256) {
        bool w = truthy32(written, p);
        bool in_ring = (p >= ring_base) && (p < ring_base + TPF);
        bool mw = in_ring ? false : w;
        bool wr = w || (!frozen && in_ring);
        out[off_mask + p] = mw ? 1.0f : 0.0f;
        out[off_wr   + p] = wr ? 1.0f : 0.0f;
    }

    // per-128-token block any/all of mask_written
    for (int b = tid; b < KVB; b += 256) {
        unsigned char any_ = 0, all_ = 1;
        #pragma unroll 4
        for (int j = 0; j < BSZ; j++) {
            int p = b * BSZ + j;
            bool in_ring = (p >= ring_base) && (p < ring_base + TPF);
            unsigned char m = in_ring ? 0 : (truthy32(written, p) ? 1 : 0);
            any_ |= m;
            all_ &= m;
        }
        s_any[b] = any_;
        s_all[b] = all_;
    }
    __syncthreads();

    // stable ordering: true blocks first (orig order), then false blocks
    if (tid == 0) {
        int np = 0, nf = 0;
        for (int b = 0; b < KVB; b++)
            if (s_any[b] && !s_all[b]) s_ordp[np++] = (short)b;
        { int k = np;
          for (int b = 0; b < KVB; b++)
              if (!(s_any[b] && !s_all[b])) s_ordp[k++] = (short)b; }
        for (int b = 0; b < KVB; b++)
            if (s_all[b]) s_ordf[nf++] = (short)b;
        { int k = nf;
          for (int b = 0; b < KVB; b++)
              if (!s_all[b]) s_ordf[k++] = (short)b; }
        s_np = np; s_nf = nf;
    }
    __syncthreads();

    float fnp = (float)s_np, fnf = (float)s_nf;
    if (tid < QB) {
        out[off_kvnum + tid] = fnp;
        out[off_fnum  + tid] = fnf;
    }
    // QB*KVB = 528 entries each, coalesced parallel writes
    for (int e = tid; e < QB * KVB; e += 256) {
        int b = e % KVB;
        out[off_kvidx + e] = (float)s_ordp[b];
        out[off_fidx  + e] = (float)s_ordf[b];
    }
}

// ---- fused kernel: grid (NCHUNKS+1, ROWS); last x-column block 0 does meta ----
__global__ void __launch_bounds__(256)
fused_kernel(const float4*       __restrict__ kv,
             const float4*       __restrict__ buf,
             const int*          __restrict__ t_pos,
             const unsigned int* __restrict__ written,
             const int*          __restrict__ frozen_p,
             float4*             __restrict__ out)
{
    if (blockIdx.x == NCHUNKS) {
        if (blockIdx.y == 0)
            do_meta(t_pos, written, frozen_p, (float*)out);
        return;
    }

    int row  = blockIdx.y;
    int base = blockIdx.x * CHUNK + threadIdx.x;

    int frame_t   = __ldg(t_pos);
    int ring_base = (frame_t % NBUCK) * TPF;
    int frozen    = frozen_p ? __ldg(frozen_p) : 0;

    const size_t rowo = (size_t)row * ROW_V4;
    const size_t kvo  = (size_t)row * KVROW_V4;

    #pragma unroll
    for (int u = 0; u < 4; u++) {
        int i = base + u * 256;
        int pos = i >> 5;                // token slot (warp-uniform)
        size_t oidx = rowo + i;
        float4 val;
        if (pos >= LL) {
            val = __ldcs(&kv[kvo + (i - LL * 32)]);
        } else if (!frozen && pos >= ring_base && pos < ring_base + TPF) {
            val = __ldcs(&kv[kvo + (i - ring_base * 32)]);
        } else {
            val = __ldcs(&buf[oidx]);
        }
        __stcs(&out[oidx], val);
    }
}

extern "C" void kernel_launch(void* const* d_in, const int* in_sizes, int n_in,
                              void* d_out, int out_size)
{
    const float4*       kv     = (const float4*)d_in[0];
    const float4*       buf    = (const float4*)d_in[1];
    const int*          t_pos  = (const int*)d_in[2];
    const unsigned int* wrt    = (const unsigned int*)d_in[3];
    const int*          frozen = (n_in > 4) ? (const int*)d_in[4] : nullptr;

    (void)in_sizes; (void)out_size;

    dim3 grid(NCHUNKS + 1, ROWS);   // (529, 64)
    fused_kernel<<<grid, 256>>>(kv, buf, t_pos, wrt, frozen, (float4*)d_out);
}